// round 5
// baseline (speedup 1.0000x reference)
#include <cuda_runtime.h>
#include <cstdint>
#include <cstddef>

// ---------------------------------------------------------------------------
// DataDependentRBFKernel
//   sigma = MLP(embeddings)  (256 -> 32 -> 16 -> 1, exact gelu, sigmoid,
//                             affine to [0.1, 10])
//   out[b,n,m] = exp(-||z[m] - mu[b,n]||^2 / (2 sigma[b,n]^2))
//
// sigma_kernel: smem-staged MLP, 16 rows per 128-thread block (grid 512,
//               all blocks resident in one wave). Folds mu into per-row
//               coefficients (sc, c0, c1, cc) -> g_coef.
// rbf_kernel:   8 rows x full M per 256-thread block (grid 1024),
//               8 pts/thread -> 2 independent STG.128 chains per row.
// ---------------------------------------------------------------------------

#define EDIM 256
#define H1DIM 32
#define H2DIM 16
#define SROWS 16

__device__ float4 g_coef[8192];   // per-row (sc, c0, c1, cc)

__device__ __forceinline__ float ex2_approx(float x) {
    float y;
    asm("ex2.approx.f32 %0, %1;" : "=f"(y) : "f"(x));
    return y;
}

__device__ __forceinline__ float gelu_exact(float x) {
    return 0.5f * x * (1.0f + erff(x * 0.70710678118654752440f));
}

// -------------------- sigma MLP: 16 rows per 128-thread block --------------
// Dynamic smem (floats): e_s[16*256] 16KB | w1_s[256*32] 32KB ([k][j])
//                        | w2_s[32*16] 2KB | h1_s[16*32] | h2_s[16*16]
__global__ __launch_bounds__(128)
void sigma_kernel(const float* __restrict__ emb, const float* __restrict__ mu,
                  const float* __restrict__ w1, const float* __restrict__ b1,
                  const float* __restrict__ w2, const float* __restrict__ b2,
                  const float* __restrict__ w3, const float* __restrict__ b3)
{
    extern __shared__ float smem[];
    float* e_s  = smem;                       // 4096
    float* w1_s = e_s + SROWS * EDIM;         // 8192
    float* w2_s = w1_s + EDIM * H1DIM;        // 512
    float* h1_s = w2_s + H1DIM * H2DIM;       // 512
    float* h2_s = h1_s + SROWS * H1DIM;       // 256

    const int tid = threadIdx.x;
    const int rowbase = blockIdx.x * SROWS;

    // ---- cooperative staging (float4, coalesced) ----
    {
        const float4* e4 = reinterpret_cast<const float4*>(emb + (size_t)rowbase * EDIM);
        float4* es4 = reinterpret_cast<float4*>(e_s);
        #pragma unroll
        for (int i = 0; i < (SROWS * EDIM / 4) / 128; ++i)   // 8
            es4[tid + i * 128] = e4[tid + i * 128];

        const float4* w14 = reinterpret_cast<const float4*>(w1);
        float4* w1s4 = reinterpret_cast<float4*>(w1_s);
        #pragma unroll
        for (int i = 0; i < (EDIM * H1DIM / 4) / 128; ++i)   // 16
            w1s4[tid + i * 128] = w14[tid + i * 128];

        if (tid < (H1DIM * H2DIM / 4))                        // 128
            reinterpret_cast<float4*>(w2_s)[tid] =
                reinterpret_cast<const float4*>(w2)[tid];
    }
    __syncthreads();

    // ---- layer 1: warp w -> rows 4w..4w+3, lane = unit j ----
    {
        const int j = tid & 31;
        const int w = tid >> 5;            // 0..3
        const float* e0 = e_s + (w * 4) * EDIM;

        float acc0, acc1, acc2, acc3;
        acc0 = acc1 = acc2 = acc3 = __ldg(&b1[j]);

        #pragma unroll 8
        for (int k = 0; k < EDIM; k += 4) {
            const float wv0 = w1_s[(k + 0) * H1DIM + j];
            const float wv1 = w1_s[(k + 1) * H1DIM + j];
            const float wv2 = w1_s[(k + 2) * H1DIM + j];
            const float wv3 = w1_s[(k + 3) * H1DIM + j];
            float4 e;
            e = *reinterpret_cast<const float4*>(e0 + 0 * EDIM + k);
            acc0 = fmaf(e.x, wv0, acc0); acc0 = fmaf(e.y, wv1, acc0);
            acc0 = fmaf(e.z, wv2, acc0); acc0 = fmaf(e.w, wv3, acc0);
            e = *reinterpret_cast<const float4*>(e0 + 1 * EDIM + k);
            acc1 = fmaf(e.x, wv0, acc1); acc1 = fmaf(e.y, wv1, acc1);
            acc1 = fmaf(e.z, wv2, acc1); acc1 = fmaf(e.w, wv3, acc1);
            e = *reinterpret_cast<const float4*>(e0 + 2 * EDIM + k);
            acc2 = fmaf(e.x, wv0, acc2); acc2 = fmaf(e.y, wv1, acc2);
            acc2 = fmaf(e.z, wv2, acc2); acc2 = fmaf(e.w, wv3, acc2);
            e = *reinterpret_cast<const float4*>(e0 + 3 * EDIM + k);
            acc3 = fmaf(e.x, wv0, acc3); acc3 = fmaf(e.y, wv1, acc3);
            acc3 = fmaf(e.z, wv2, acc3); acc3 = fmaf(e.w, wv3, acc3);
        }
        h1_s[(w * 4 + 0) * H1DIM + j] = gelu_exact(acc0);
        h1_s[(w * 4 + 1) * H1DIM + j] = gelu_exact(acc1);
        h1_s[(w * 4 + 2) * H1DIM + j] = gelu_exact(acc2);
        h1_s[(w * 4 + 3) * H1DIM + j] = gelu_exact(acc3);
    }
    __syncthreads();

    // ---- layer 2: 16 rows x 16 units = 256 items, 2 per thread ----
    {
        #pragma unroll
        for (int it = 0; it < 2; ++it) {
            const int item = tid + it * 128;
            const int r = item >> 4;
            const int m = item & 15;
            float acc = __ldg(&b2[m]);
            #pragma unroll
            for (int j = 0; j < H1DIM; ++j)
                acc = fmaf(h1_s[r * H1DIM + j], w2_s[j * H2DIM + m], acc);
            h2_s[r * H2DIM + m] = gelu_exact(acc);
        }
    }
    __syncthreads();

    // ---- layer 3 + sigmoid + affine + fold mu into coefficients ----
    if (tid < SROWS) {
        float s = __ldg(&b3[0]);
        #pragma unroll
        for (int m = 0; m < H2DIM; ++m)
            s = fmaf(h2_s[tid * H2DIM + m], __ldg(&w3[m]), s);
        const float sig = 1.0f / (1.0f + expf(-s));
        const float sigma = 0.1f + 9.9f * sig;
        const float sc = -1.44269504088896340736f / (2.0f * sigma * sigma);
        const float2 muv = reinterpret_cast<const float2*>(mu)[rowbase + tid];
        const float c0 = -2.0f * sc * muv.x;
        const float c1 = -2.0f * sc * muv.y;
        const float cc = sc * (muv.x * muv.x + muv.y * muv.y);
        g_coef[rowbase + tid] = make_float4(sc, c0, c1, cc);
    }
}

// -------------------- RBF sweep: 8 rows x full M per 256-thread block ------
// Thread t owns 8 contiguous z points (registers); per row: 24 FMA, 8 MUFU,
// 2 independent STG.128. Grid = BN/8 = 1024 blocks.
__global__ __launch_bounds__(256)
void rbf_kernel(const float* __restrict__ z, float* __restrict__ out, int M)
{
    constexpr int TILE_R = 8;
    __shared__ float4 coef_s[TILE_R];

    const int t = threadIdx.x;
    const int rowbase = blockIdx.x * TILE_R;

    if (t < TILE_R)
        coef_s[t] = g_coef[rowbase + t];

    // 8 z points: z is [M,2] interleaved -> 4 float4 loads
    float z0[8], z1[8], r2[8];
    {
        const float4* z4 = reinterpret_cast<const float4*>(z);
        #pragma unroll
        for (int i = 0; i < 4; ++i) {
            float4 v = z4[t * 4 + i];
            z0[2 * i]     = v.x;  z1[2 * i]     = v.y;
            z0[2 * i + 1] = v.z;  z1[2 * i + 1] = v.w;
        }
        #pragma unroll
        for (int i = 0; i < 8; ++i)
            r2[i] = z0[i] * z0[i] + z1[i] * z1[i];
    }
    __syncthreads();

    float* optr = out + (size_t)rowbase * (size_t)M + (size_t)t * 8;

    #pragma unroll
    for (int r = 0; r < TILE_R; ++r) {
        const float4 c = coef_s[r];
        float o[8];
        #pragma unroll
        for (int i = 0; i < 8; ++i) {
            float a = fmaf(c.x, r2[i], fmaf(c.y, z0[i], fmaf(c.z, z1[i], c.w)));
            o[i] = ex2_approx(a);
        }
        float4* o4 = reinterpret_cast<float4*>(optr);
        o4[0] = make_float4(o[0], o[1], o[2], o[3]);
        o4[1] = make_float4(o[4], o[5], o[6], o[7]);
        optr += M;
    }
}

// ---------------------------------------------------------------------------
extern "C" void kernel_launch(void* const* d_in, const int* in_sizes, int n_in,
                              void* d_out, int out_size)
{
    const float* z   = (const float*)d_in[0];   // [M, 2]
    const float* mu  = (const float*)d_in[1];   // [B, N, 2]
    const float* emb = (const float*)d_in[2];   // [B, N, 256]
    const float* w1  = (const float*)d_in[3];   // [256, 32]
    const float* b1  = (const float*)d_in[4];   // [32]
    const float* w2  = (const float*)d_in[5];   // [32, 16]
    const float* b2  = (const float*)d_in[6];   // [16]
    const float* w3  = (const float*)d_in[7];   // [16, 1]
    const float* b3  = (const float*)d_in[8];   // [1]
    float* out = (float*)d_out;

    const int M  = in_sizes[0] / 2;   // 2048
    const int BN = in_sizes[1] / 2;   // 8192

    const int smem_bytes = (SROWS * EDIM + EDIM * H1DIM + H1DIM * H2DIM +
                            SROWS * H1DIM + SROWS * H2DIM) * sizeof(float);
    static bool attr_set = false;
    if (!attr_set) {
        cudaFuncSetAttribute(sigma_kernel,
                             cudaFuncAttributeMaxDynamicSharedMemorySize,
                             smem_bytes);
        attr_set = true;
    }

    sigma_kernel<<<8192 / SROWS, 128, smem_bytes>>>(emb, mu, w1, b1, w2, b2, w3, b3);

    rbf_kernel<<<BN / 8, 256>>>(z, out, M);
}

// round 6
// speedup vs baseline: 1.2039x; 1.2039x over previous
#include <cuda_runtime.h>
#include <cstdint>
#include <cstddef>

// ---------------------------------------------------------------------------
// DataDependentRBFKernel
//   sigma = MLP(embeddings)  (256 -> 32 -> 16 -> 1, exact gelu, sigmoid,
//                             affine to [0.1, 10])
//   out[b,n,m] = exp(-||z[m] - mu[b,n]||^2 / (2 sigma[b,n]^2))
//
// sigma_kernel: smem-staged MLP, 16 rows per 256-thread block, split-K:
//               warp w -> row-group (w>>1), k-half (w&1). Partials reduced
//               in smem. Folds mu into per-row (sc,c0,c1,cc) -> g_coef.
// rbf_kernel:   proven R2 config: 8 rows x 1024 z per 256-thread block,
//               4 pts/thread, grid (2, 1024); coef via uniform __ldg.
// ---------------------------------------------------------------------------

#define EDIM 256
#define H1DIM 32
#define H2DIM 16
#define SROWS 16

__device__ float4 g_coef[8192];   // per-row (sc, c0, c1, cc)

__device__ __forceinline__ float ex2_approx(float x) {
    float y;
    asm("ex2.approx.f32 %0, %1;" : "=f"(y) : "f"(x));
    return y;
}

__device__ __forceinline__ float gelu_exact(float x) {
    return 0.5f * x * (1.0f + erff(x * 0.70710678118654752440f));
}

// -------------------- sigma MLP: 16 rows per 256-thread block, split-K -----
// Dynamic smem (floats):
//   e_s   [16*256] 16KB | w1_s [256*32] 32KB ([k][j], j contiguous)
//   w2_s  [32*16]   2KB | ps   [2*16*32] 4KB | h1_s [16*32] | h2_s [16*16]
__global__ __launch_bounds__(256)
void sigma_kernel(const float* __restrict__ emb, const float* __restrict__ mu,
                  const float* __restrict__ w1, const float* __restrict__ b1,
                  const float* __restrict__ w2, const float* __restrict__ b2,
                  const float* __restrict__ w3, const float* __restrict__ b3)
{
    extern __shared__ float smem[];
    float* e_s  = smem;                        // 4096
    float* w1_s = e_s + SROWS * EDIM;          // 8192
    float* w2_s = w1_s + EDIM * H1DIM;         // 512
    float* ps   = w2_s + H1DIM * H2DIM;        // 1024 (2 halves x 16 rows x 32)
    float* h1_s = ps + 2 * SROWS * H1DIM;      // 512
    float* h2_s = h1_s + SROWS * H1DIM;        // 256

    const int tid = threadIdx.x;
    const int rowbase = blockIdx.x * SROWS;

    // ---- cooperative staging (float4, coalesced) ----
    {
        const float4* e4 = reinterpret_cast<const float4*>(emb + (size_t)rowbase * EDIM);
        float4* es4 = reinterpret_cast<float4*>(e_s);
        #pragma unroll
        for (int i = 0; i < (SROWS * EDIM / 4) / 256; ++i)   // 4
            es4[tid + i * 256] = e4[tid + i * 256];

        const float4* w14 = reinterpret_cast<const float4*>(w1);
        float4* w1s4 = reinterpret_cast<float4*>(w1_s);
        #pragma unroll
        for (int i = 0; i < (EDIM * H1DIM / 4) / 256; ++i)   // 8
            w1s4[tid + i * 256] = w14[tid + i * 256];

        if (tid < (H1DIM * H2DIM / 4))                        // 128
            reinterpret_cast<float4*>(w2_s)[tid] =
                reinterpret_cast<const float4*>(w2)[tid];
    }
    __syncthreads();

    // ---- layer 1, split-K: warp w -> rows 4*(w>>1)..+3, k-half (w&1) ----
    {
        const int j = tid & 31;
        const int w = tid >> 5;            // 0..7
        const int g = w >> 1;              // row group 0..3
        const int h = w & 1;               // k half
        const float* e0 = e_s + (g * 4) * EDIM + h * (EDIM / 2);
        const float* w1h = w1_s + h * (EDIM / 2) * H1DIM;

        float acc0 = 0.f, acc1 = 0.f, acc2 = 0.f, acc3 = 0.f;

        #pragma unroll 8
        for (int k = 0; k < EDIM / 2; k += 4) {
            const float wv0 = w1h[(k + 0) * H1DIM + j];
            const float wv1 = w1h[(k + 1) * H1DIM + j];
            const float wv2 = w1h[(k + 2) * H1DIM + j];
            const float wv3 = w1h[(k + 3) * H1DIM + j];
            float4 e;
            e = *reinterpret_cast<const float4*>(e0 + 0 * EDIM + k);
            acc0 = fmaf(e.x, wv0, acc0); acc0 = fmaf(e.y, wv1, acc0);
            acc0 = fmaf(e.z, wv2, acc0); acc0 = fmaf(e.w, wv3, acc0);
            e = *reinterpret_cast<const float4*>(e0 + 1 * EDIM + k);
            acc1 = fmaf(e.x, wv0, acc1); acc1 = fmaf(e.y, wv1, acc1);
            acc1 = fmaf(e.z, wv2, acc1); acc1 = fmaf(e.w, wv3, acc1);
            e = *reinterpret_cast<const float4*>(e0 + 2 * EDIM + k);
            acc2 = fmaf(e.x, wv0, acc2); acc2 = fmaf(e.y, wv1, acc2);
            acc2 = fmaf(e.z, wv2, acc2); acc2 = fmaf(e.w, wv3, acc2);
            e = *reinterpret_cast<const float4*>(e0 + 3 * EDIM + k);
            acc3 = fmaf(e.x, wv0, acc3); acc3 = fmaf(e.y, wv1, acc3);
            acc3 = fmaf(e.z, wv2, acc3); acc3 = fmaf(e.w, wv3, acc3);
        }
        ps[((h * SROWS) + g * 4 + 0) * H1DIM + j] = acc0;
        ps[((h * SROWS) + g * 4 + 1) * H1DIM + j] = acc1;
        ps[((h * SROWS) + g * 4 + 2) * H1DIM + j] = acc2;
        ps[((h * SROWS) + g * 4 + 3) * H1DIM + j] = acc3;
    }
    __syncthreads();

    // ---- reduce halves + gelu: 16 rows x 32 j = 512 = 2 per thread ----
    {
        #pragma unroll
        for (int it = 0; it < 2; ++it) {
            const int item = tid + it * 256;
            const int r = item >> 5;
            const int j = item & 31;
            const float v = __ldg(&b1[j]) + ps[r * H1DIM + j]
                          + ps[(SROWS + r) * H1DIM + j];
            h1_s[r * H1DIM + j] = gelu_exact(v);
        }
    }
    __syncthreads();

    // ---- layer 2: 16 rows x 16 units = 256 items, 1 per thread ----
    {
        const int r = tid >> 4;
        const int m = tid & 15;
        float acc = __ldg(&b2[m]);
        #pragma unroll
        for (int j = 0; j < H1DIM; ++j)
            acc = fmaf(h1_s[r * H1DIM + j], w2_s[j * H2DIM + m], acc);
        h2_s[r * H2DIM + m] = gelu_exact(acc);
    }
    __syncthreads();

    // ---- layer 3 + sigmoid + affine + fold mu into coefficients ----
    if (tid < SROWS) {
        float s = __ldg(&b3[0]);
        #pragma unroll
        for (int m = 0; m < H2DIM; ++m)
            s = fmaf(h2_s[tid * H2DIM + m], __ldg(&w3[m]), s);
        const float sig = 1.0f / (1.0f + expf(-s));
        const float sigma = 0.1f + 9.9f * sig;
        const float sc = -1.44269504088896340736f / (2.0f * sigma * sigma);
        const float2 muv = reinterpret_cast<const float2*>(mu)[rowbase + tid];
        const float c0 = -2.0f * sc * muv.x;
        const float c1 = -2.0f * sc * muv.y;
        const float cc = sc * (muv.x * muv.x + muv.y * muv.y);
        g_coef[rowbase + tid] = make_float4(sc, c0, c1, cc);
    }
}

// -------------------- RBF sweep: 8 rows x 1024 z per 256-thread block ------
// Proven R2 shape. coef read via uniform __ldg (warp broadcast, L1 hit);
// no smem, no barrier.
__global__ __launch_bounds__(256)
void rbf_kernel(const float* __restrict__ z, float* __restrict__ out, int M)
{
    constexpr int TILE_R = 8;

    const int t = threadIdx.x;
    const int zb = blockIdx.x * 1024 + t * 4;
    const int rowbase = blockIdx.y * TILE_R;

    // 4 z points: z is [M,2] interleaved -> 2 float4 loads
    float z0[4], z1[4], r2[4];
    {
        const float4* z4 = reinterpret_cast<const float4*>(z);
        #pragma unroll
        for (int i = 0; i < 2; ++i) {
            float4 v = z4[(size_t)(blockIdx.x * 512) + (size_t)t * 2 + i];
            z0[2 * i]     = v.x;  z1[2 * i]     = v.y;
            z0[2 * i + 1] = v.z;  z1[2 * i + 1] = v.w;
        }
        #pragma unroll
        for (int i = 0; i < 4; ++i)
            r2[i] = z0[i] * z0[i] + z1[i] * z1[i];
    }

    float* optr = out + (size_t)rowbase * (size_t)M + (size_t)zb;

    #pragma unroll
    for (int r = 0; r < TILE_R; ++r) {
        const float4 c = __ldg(&g_coef[rowbase + r]);   // uniform -> broadcast
        float o[4];
        #pragma unroll
        for (int i = 0; i < 4; ++i) {
            float a = fmaf(c.x, r2[i], fmaf(c.y, z0[i], fmaf(c.z, z1[i], c.w)));
            o[i] = ex2_approx(a);
        }
        *reinterpret_cast<float4*>(optr) = make_float4(o[0], o[1], o[2], o[3]);
        optr += M;
    }
}

// ---------------------------------------------------------------------------
extern "C" void kernel_launch(void* const* d_in, const int* in_sizes, int n_in,
                              void* d_out, int out_size)
{
    const float* z   = (const float*)d_in[0];   // [M, 2]
    const float* mu  = (const float*)d_in[1];   // [B, N, 2]
    const float* emb = (const float*)d_in[2];   // [B, N, 256]
    const float* w1  = (const float*)d_in[3];   // [256, 32]
    const float* b1  = (const float*)d_in[4];   // [32]
    const float* w2  = (const float*)d_in[5];   // [32, 16]
    const float* b2  = (const float*)d_in[6];   // [16]
    const float* w3  = (const float*)d_in[7];   // [16, 1]
    const float* b3  = (const float*)d_in[8];   // [1]
    float* out = (float*)d_out;

    const int M  = in_sizes[0] / 2;   // 2048
    const int BN = in_sizes[1] / 2;   // 8192

    const int smem_bytes = (SROWS * EDIM + EDIM * H1DIM + H1DIM * H2DIM +
                            2 * SROWS * H1DIM + SROWS * H1DIM + SROWS * H2DIM)
                           * sizeof(float);
    static bool attr_set = false;
    if (!attr_set) {
        cudaFuncSetAttribute(sigma_kernel,
                             cudaFuncAttributeMaxDynamicSharedMemorySize,
                             smem_bytes);
        attr_set = true;
    }

    sigma_kernel<<<BN / SROWS, 256, smem_bytes>>>(emb, mu, w1, b1, w2, b2, w3, b3);

    dim3 grid(M / 1024, BN / 8);
    rbf_kernel<<<grid, 256>>>(z, out, M);
}